// round 4
// baseline (speedup 1.0000x reference)
#include <cuda_runtime.h>
#include <math.h>

#define D_MODEL 1024
#define NHEADS  16
#define HD      64
#define SEQ     2048
#define BATCH   2
#define WIN     256

// Scratch (allocation-free: __device__ globals).
// All of these hold tf32-rounded values (bit patterns valid as mma operands).
__device__ float g_Q[BATCH * NHEADS * SEQ * HD];   // [b][h][l][d]
__device__ float g_K[BATCH * NHEADS * SEQ * HD];
__device__ float g_V[BATCH * NHEADS * SEQ * HD];
__device__ float g_O[BATCH * SEQ * D_MODEL];       // [b][l][h*64+d]
// Pre-converted tf32 copies of the inputs
__device__ unsigned c_x [BATCH * SEQ * D_MODEL];
__device__ unsigned c_w1[3 * D_MODEL * D_MODEL];
__device__ unsigned c_w2[D_MODEL * D_MODEL];

__device__ __forceinline__ unsigned f2tf32(float f) {
    unsigned r;
    asm("cvt.rna.tf32.f32 %0, %1;" : "=r"(r) : "f"(f));
    return r;
}

__device__ __forceinline__ void mma_tf32(float c[4], const unsigned a[4], const unsigned b[2]) {
    asm volatile(
        "mma.sync.aligned.m16n8k8.row.col.f32.tf32.tf32.f32 "
        "{%0,%1,%2,%3}, {%4,%5,%6,%7}, {%8,%9}, {%0,%1,%2,%3};\n"
        : "+f"(c[0]), "+f"(c[1]), "+f"(c[2]), "+f"(c[3])
        : "r"(a[0]), "r"(a[1]), "r"(a[2]), "r"(a[3]),
          "r"(b[0]), "r"(b[1]));
}

// ---------------------------------------------------------------------------
// fp32 -> tf32 bulk converter (vectorized, grid-stride)
// ---------------------------------------------------------------------------
__global__ void cvt_tf32(const float4* __restrict__ in, uint4* __restrict__ out, int n4)
{
    int i = blockIdx.x * blockDim.x + threadIdx.x;
    if (i < n4) {
        float4 v = in[i];
        uint4 u;
        u.x = f2tf32(v.x); u.y = f2tf32(v.y);
        u.z = f2tf32(v.z); u.w = f2tf32(v.w);
        out[i] = u;
    }
}

// ---------------------------------------------------------------------------
// TF32 NT GEMM with 2-stage cp.async pipeline.
// C[m,n] = sum_k A[m,k]*W[n,k] + bias[n].
// Operands are pre-converted tf32 bits. BM=BN=128, BK=32, 256 thr, 8 warps 2x4.
// MODE 0: A=c_x, routes into g_Q/g_K/g_V (tf32-rounded).
// MODE 1: A=g_O (tf32 bits), writes fp32 Cout.
// ---------------------------------------------------------------------------
#define SSTR 36
#define STG_WORDS (128 * SSTR)

template <int MODE>
__global__ __launch_bounds__(256)
void gemm_tf32(const unsigned* __restrict__ A, const unsigned* __restrict__ W,
               const float* __restrict__ bias, float* __restrict__ Cout,
               int M, int N, int K)
{
    extern __shared__ unsigned sh[];
    unsigned* AsBase = sh;                    // 2 stages of A
    unsigned* BsBase = sh + 2 * STG_WORDS;    // 2 stages of B

    const unsigned* Ap = (MODE == 1) ? (const unsigned*)g_O : A;

    int tid  = threadIdx.x;
    int lane = tid & 31;
    int wid  = tid >> 5;
    int wm = (wid >> 2) * 64;
    int wn = (wid & 3) * 32;
    int bm = blockIdx.y * 128;
    int bn = blockIdx.x * 128;
    int g = lane >> 2;
    int t = lane & 3;

    int lrow = tid >> 3;          // 0..31
    int lc4  = (tid & 7) * 4;     // 0..28

    float acc[4][4][4];
#pragma unroll
    for (int mt = 0; mt < 4; mt++)
#pragma unroll
        for (int nt = 0; nt < 4; nt++)
#pragma unroll
            for (int i = 0; i < 4; i++) acc[mt][nt][i] = 0.f;

    // issue one stage of async loads
    auto issue = [&](int s, int k0) {
        unsigned* dA = AsBase + s * STG_WORDS;
        unsigned* dB = BsBase + s * STG_WORDS;
#pragma unroll
        for (int r = 0; r < 4; r++) {
            int rr = lrow + r * 32;
            const unsigned* ga = Ap + (size_t)(bm + rr) * K + k0 + lc4;
            const unsigned* gb = W  + (size_t)(bn + rr) * K + k0 + lc4;
            unsigned sa = (unsigned)__cvta_generic_to_shared(&dA[rr * SSTR + lc4]);
            unsigned sb = (unsigned)__cvta_generic_to_shared(&dB[rr * SSTR + lc4]);
            asm volatile("cp.async.cg.shared.global [%0], [%1], 16;\n" :: "r"(sa), "l"(ga));
            asm volatile("cp.async.cg.shared.global [%0], [%1], 16;\n" :: "r"(sb), "l"(gb));
        }
        asm volatile("cp.async.commit_group;\n");
    };

    issue(0, 0);
    int stage = 0;

    for (int k0 = 0; k0 < K; k0 += 32) {
        bool more = (k0 + 32 < K);
        if (more) issue(stage ^ 1, k0 + 32);
        if (more) asm volatile("cp.async.wait_group 1;\n");
        else      asm volatile("cp.async.wait_group 0;\n");
        __syncthreads();

        const unsigned* As = AsBase + stage * STG_WORDS;
        const unsigned* Bs = BsBase + stage * STG_WORDS;

#pragma unroll
        for (int ks = 0; ks < 4; ks++) {
            int kk = ks * 8;
            unsigned af[4][4], bf[4][2];
#pragma unroll
            for (int mt = 0; mt < 4; mt++) {
                int r = wm + mt * 16 + g;
                int c = kk + t;
                af[mt][0] = As[r * SSTR + c];
                af[mt][1] = As[(r + 8) * SSTR + c];
                af[mt][2] = As[r * SSTR + c + 4];
                af[mt][3] = As[(r + 8) * SSTR + c + 4];
            }
#pragma unroll
            for (int nt = 0; nt < 4; nt++) {
                int n = wn + nt * 8 + g;
                int c = kk + t;
                bf[nt][0] = Bs[n * SSTR + c];
                bf[nt][1] = Bs[n * SSTR + c + 4];
            }
#pragma unroll
            for (int mt = 0; mt < 4; mt++)
#pragma unroll
                for (int nt = 0; nt < 4; nt++)
                    mma_tf32(acc[mt][nt], af[mt], bf[nt]);
        }
        __syncthreads();
        stage ^= 1;
    }

#pragma unroll
    for (int mt = 0; mt < 4; mt++) {
#pragma unroll
        for (int nt = 0; nt < 4; nt++) {
#pragma unroll
            for (int i = 0; i < 4; i++) {
                int m = bm + wm + mt * 16 + g + ((i >> 1) ? 8 : 0);
                int n = bn + wn + nt * 8 + t * 2 + (i & 1);
                float v = acc[mt][nt][i] + bias[n];
                if (MODE == 0) {
                    int part   = n >> 10;
                    int within = n & 1023;
                    int h = within >> 6;
                    int d = within & 63;
                    int b = m >> 11;
                    int l = m & 2047;
                    size_t dst = ((size_t)(b * NHEADS + h) * SEQ + l) * HD + d;
                    float* base = (part == 0) ? g_Q : (part == 1) ? g_K : g_V;
                    base[dst] = __uint_as_float(f2tf32(v));   // already tf32 for attn
                } else {
                    Cout[(size_t)m * N + n] = v;
                }
            }
        }
    }
}

// ---------------------------------------------------------------------------
// Sliding-window attention with tf32 tensor cores.
// Q/K/V arrive already tf32-rounded -> smem staging is raw bit copies.
// One CTA = (b*h, 64-query tile), 128 threads (4 warps, warp = 16 query rows).
// ---------------------------------------------------------------------------
#define AST 68

__global__ __launch_bounds__(128)
void attn_mma()
{
    extern __shared__ unsigned smu[];
    unsigned* Qs = smu;                 // [q][d]  64 x 68
    unsigned* Ks = smu + 64 * AST;      // [j][d]
    unsigned* Vt = smu + 2 * 64 * AST;  // [d][j]
    unsigned* Ps = smu + 3 * 64 * AST;  // [q][j]

    int tid  = threadIdx.x;
    int lane = tid & 31;
    int wid  = tid >> 5;
    int g = lane >> 2;
    int t = lane & 3;

    int bh = blockIdx.y;
    int i0 = blockIdx.x * 64;

    const float* Qg = g_Q + (size_t)bh * SEQ * HD;
    const float* Kg = g_K + (size_t)bh * SEQ * HD;
    const float* Vg = g_V + (size_t)bh * SEQ * HD;

    // Load Q tile, scale by 0.125 (exact: exponent shift keeps tf32 mantissa)
    {
        int q = tid >> 1, half = tid & 1;
#pragma unroll
        for (int v = 0; v < 8; v++) {
            int c4 = half * 32 + v * 4;
            float4 qv = *(const float4*)(Qg + (size_t)(i0 + q) * HD + c4);
            uint4 u;
            u.x = __float_as_uint(qv.x * 0.125f);
            u.y = __float_as_uint(qv.y * 0.125f);
            u.z = __float_as_uint(qv.z * 0.125f);
            u.w = __float_as_uint(qv.w * 0.125f);
            *(uint4*)&Qs[q * AST + c4] = u;
        }
    }

    int rbase = wid * 16;
    int iq0 = i0 + rbase + g;
    int iq1 = iq0 + 8;

    float m0 = -1e30f, m1 = -1e30f, l0 = 0.f, l1 = 0.f;
    float oacc[8][4];
#pragma unroll
    for (int nt = 0; nt < 8; nt++)
#pragma unroll
        for (int i = 0; i < 4; i++) oacc[nt][i] = 0.f;

    int kv_lo = i0 - (WIN - 1);
    if (kv_lo < 0) kv_lo = 0;
    int cs0 = (kv_lo / 64) * 64;

    for (int cs = cs0; cs <= i0; cs += 64) {
        __syncthreads();
        // Stage K [j][d] and V transposed [d][j] — raw tf32 bit copies
        {
            int j = tid >> 1, half = tid & 1;
#pragma unroll
            for (int v = 0; v < 8; v++) {
                int c4 = half * 32 + v * 4;
                *(uint4*)&Ks[j * AST + c4] =
                    *(const uint4*)(Kg + (size_t)(cs + j) * HD + c4);
                uint4 vv = *(const uint4*)(Vg + (size_t)(cs + j) * HD + c4);
                Vt[(c4 + 0) * AST + j] = vv.x;
                Vt[(c4 + 1) * AST + j] = vv.y;
                Vt[(c4 + 2) * AST + j] = vv.z;
                Vt[(c4 + 3) * AST + j] = vv.w;
            }
        }
        __syncthreads();

        // S = Q*K^T
        float sacc[8][4];
#pragma unroll
        for (int nt = 0; nt < 8; nt++)
#pragma unroll
            for (int i = 0; i < 4; i++) sacc[nt][i] = 0.f;

#pragma unroll
        for (int kk = 0; kk < 8; kk++) {
            int c = kk * 8 + t;
            unsigned af[4];
            af[0] = Qs[(rbase + g) * AST + c];
            af[1] = Qs[(rbase + g + 8) * AST + c];
            af[2] = Qs[(rbase + g) * AST + c + 4];
            af[3] = Qs[(rbase + g + 8) * AST + c + 4];
#pragma unroll
            for (int nt = 0; nt < 8; nt++) {
                unsigned bf[2];
                bf[0] = Ks[(nt * 8 + g) * AST + c];
                bf[1] = Ks[(nt * 8 + g) * AST + c + 4];
                mma_tf32(sacc[nt], af, bf);
            }
        }

        // Mask + online softmax
        float rmax0 = -1e30f, rmax1 = -1e30f;
#pragma unroll
        for (int nt = 0; nt < 8; nt++) {
#pragma unroll
            for (int e = 0; e < 2; e++) {
                int j = cs + nt * 8 + 2 * t + e;
                if (!((j <= iq0) && (j > iq0 - WIN))) sacc[nt][e] = -1e30f;
                if (!((j <= iq1) && (j > iq1 - WIN))) sacc[nt][2 + e] = -1e30f;
                rmax0 = fmaxf(rmax0, sacc[nt][e]);
                rmax1 = fmaxf(rmax1, sacc[nt][2 + e]);
            }
        }
#pragma unroll
        for (int msk = 1; msk < 4; msk <<= 1) {
            rmax0 = fmaxf(rmax0, __shfl_xor_sync(0xffffffffu, rmax0, msk));
            rmax1 = fmaxf(rmax1, __shfl_xor_sync(0xffffffffu, rmax1, msk));
        }

        float mn0 = fmaxf(m0, rmax0);
        float mn1 = fmaxf(m1, rmax1);
        float cor0 = __expf(m0 - mn0);
        float cor1 = __expf(m1 - mn1);
        m0 = mn0; m1 = mn1;

        float rs0 = 0.f, rs1 = 0.f;
#pragma unroll
        for (int nt = 0; nt < 8; nt++) {
            float p0 = __expf(sacc[nt][0] - mn0);
            float p1 = __expf(sacc[nt][1] - mn0);
            float p2 = __expf(sacc[nt][2] - mn1);
            float p3 = __expf(sacc[nt][3] - mn1);
            rs0 += p0 + p1;
            rs1 += p2 + p3;
            int col = nt * 8 + 2 * t;
            uint2 u0 = { f2tf32(p0), f2tf32(p1) };
            uint2 u1 = { f2tf32(p2), f2tf32(p3) };
            *(uint2*)&Ps[(rbase + g) * AST + col]     = u0;
            *(uint2*)&Ps[(rbase + g + 8) * AST + col] = u1;
        }
#pragma unroll
        for (int msk = 1; msk < 4; msk <<= 1) {
            rs0 += __shfl_xor_sync(0xffffffffu, rs0, msk);
            rs1 += __shfl_xor_sync(0xffffffffu, rs1, msk);
        }
        l0 = l0 * cor0 + rs0;
        l1 = l1 * cor1 + rs1;
#pragma unroll
        for (int nt = 0; nt < 8; nt++) {
            oacc[nt][0] *= cor0; oacc[nt][1] *= cor0;
            oacc[nt][2] *= cor1; oacc[nt][3] *= cor1;
        }
        __syncwarp();

        // O += P * V
#pragma unroll
        for (int kk = 0; kk < 8; kk++) {
            int c = kk * 8 + t;
            unsigned af[4];
            af[0] = Ps[(rbase + g) * AST + c];
            af[1] = Ps[(rbase + g + 8) * AST + c];
            af[2] = Ps[(rbase + g) * AST + c + 4];
            af[3] = Ps[(rbase + g + 8) * AST + c + 4];
#pragma unroll
            for (int nt = 0; nt < 8; nt++) {
                unsigned bf[2];
                bf[0] = Vt[(nt * 8 + g) * AST + c];
                bf[1] = Vt[(nt * 8 + g) * AST + c + 4];
                mma_tf32(oacc[nt], af, bf);
            }
        }
    }

    // Normalize + write tf32-rounded O (consumed by gemm<1> as tf32 bits)
    float inv0 = 1.f / l0;
    float inv1 = 1.f / l1;
    int b = bh / NHEADS;
    int h = bh % NHEADS;
    float* O0 = g_O + (size_t)(b * SEQ + iq0) * D_MODEL + h * HD;
    float* O1 = g_O + (size_t)(b * SEQ + iq1) * D_MODEL + h * HD;
#pragma unroll
    for (int nt = 0; nt < 8; nt++) {
        int d = nt * 8 + 2 * t;
        uint2 v0 = { f2tf32(oacc[nt][0] * inv0), f2tf32(oacc[nt][1] * inv0) };
        uint2 v1 = { f2tf32(oacc[nt][2] * inv1), f2tf32(oacc[nt][3] * inv1) };
        *(uint2*)(O0 + d) = *(uint2*)&v0;
        *(uint2*)(O1 + d) = *(uint2*)&v1;
    }
}

// ---------------------------------------------------------------------------
extern "C" void kernel_launch(void* const* d_in, const int* in_sizes, int n_in,
                              void* d_out, int out_size)
{
    const float* x  = (const float*)d_in[0];   // [2,2048,1024]
    const float* w1 = (const float*)d_in[1];   // [3072,1024]
    const float* b1 = (const float*)d_in[2];   // [3072]
    const float* w2 = (const float*)d_in[3];   // [1024,1024]
    const float* b2 = (const float*)d_in[4];   // [1024]
    float* out = (float*)d_out;                // [2,2048,1024]

    const int M = BATCH * SEQ;                 // 4096

    unsigned *cx, *cw1, *cw2;
    cudaGetSymbolAddress((void**)&cx,  c_x);
    cudaGetSymbolAddress((void**)&cw1, c_w1);
    cudaGetSymbolAddress((void**)&cw2, c_w2);

    // 0) One-shot fp32 -> tf32 conversions
    {
        int n4x = M * D_MODEL / 4;
        cvt_tf32<<<(n4x + 255) / 256, 256>>>((const float4*)x, (uint4*)cx, n4x);
        int n4w1 = 3 * D_MODEL * D_MODEL / 4;
        cvt_tf32<<<(n4w1 + 255) / 256, 256>>>((const float4*)w1, (uint4*)cw1, n4w1);
        int n4w2 = D_MODEL * D_MODEL / 4;
        cvt_tf32<<<(n4w2 + 255) / 256, 256>>>((const float4*)w2, (uint4*)cw2, n4w2);
    }

    const int gemm_smem = 4 * STG_WORDS * sizeof(unsigned);   // 73728 B

    // 1) QKV projection (pipelined tf32), routed into g_Q/g_K/g_V
    {
        cudaFuncSetAttribute(gemm_tf32<0>,
                             cudaFuncAttributeMaxDynamicSharedMemorySize, gemm_smem);
        dim3 grid(3 * D_MODEL / 128, M / 128); // 24 x 32
        gemm_tf32<0><<<grid, 256, gemm_smem>>>(cx, cw1, b1, nullptr, M, 3 * D_MODEL, D_MODEL);
    }

    // 2) Sliding-window attention (tf32 tensor cores)
    {
        int smem = 4 * 64 * AST * sizeof(unsigned);  // 69632 B
        cudaFuncSetAttribute(attn_mma,
                             cudaFuncAttributeMaxDynamicSharedMemorySize, smem);
        dim3 grid(SEQ / 64, BATCH * NHEADS);   // 32 x 32
        attn_mma<<<grid, 128, smem>>>();
    }

    // 3) Output projection (pipelined tf32)
    {
        cudaFuncSetAttribute(gemm_tf32<1>,
                             cudaFuncAttributeMaxDynamicSharedMemorySize, gemm_smem);
        dim3 grid(D_MODEL / 128, M / 128);     // 8 x 32
        gemm_tf32<1><<<grid, 256, gemm_smem>>>(nullptr, cw2, b2, out, M, D_MODEL, D_MODEL);
    }
}

// round 5
// speedup vs baseline: 1.0472x; 1.0472x over previous
#include <cuda_runtime.h>
#include <math.h>

#define D_MODEL 1024
#define NHEADS  16
#define HD      64
#define SEQ     2048
#define BATCH   2
#define WIN     256

// Scratch (allocation-free: __device__ globals).
// All hold tf32-rounded values (bit patterns valid as mma operands).
__device__ float g_Q[BATCH * NHEADS * SEQ * HD];   // [b][h][l][d]
__device__ float g_K[BATCH * NHEADS * SEQ * HD];
__device__ float g_V[BATCH * NHEADS * SEQ * HD];
__device__ float g_O[BATCH * SEQ * D_MODEL];       // [b][l][h*64+d]
__device__ unsigned c_x [BATCH * SEQ * D_MODEL];
__device__ unsigned c_w1[3 * D_MODEL * D_MODEL];
__device__ unsigned c_w2[D_MODEL * D_MODEL];

__device__ __forceinline__ unsigned f2tf32(float f) {
    unsigned r;
    asm("cvt.rna.tf32.f32 %0, %1;" : "=r"(r) : "f"(f));
    return r;
}

__device__ __forceinline__ void mma_tf32(float c[4], const unsigned a[4], const unsigned b[2]) {
    asm volatile(
        "mma.sync.aligned.m16n8k8.row.col.f32.tf32.tf32.f32 "
        "{%0,%1,%2,%3}, {%4,%5,%6,%7}, {%8,%9}, {%0,%1,%2,%3};\n"
        : "+f"(c[0]), "+f"(c[1]), "+f"(c[2]), "+f"(c[3])
        : "r"(a[0]), "r"(a[1]), "r"(a[2]), "r"(a[3]),
          "r"(b[0]), "r"(b[1]));
}

__device__ __forceinline__ void ldsm_x4(unsigned a[4], unsigned saddr) {
    asm volatile("ldmatrix.sync.aligned.m8n8.x4.shared.b16 {%0,%1,%2,%3}, [%4];"
        : "=r"(a[0]), "=r"(a[1]), "=r"(a[2]), "=r"(a[3]) : "r"(saddr));
}

// ---------------------------------------------------------------------------
// fp32 -> tf32 bulk converter
// ---------------------------------------------------------------------------
__global__ void cvt_tf32(const float4* __restrict__ in, uint4* __restrict__ out, int n4)
{
    int i = blockIdx.x * blockDim.x + threadIdx.x;
    if (i < n4) {
        float4 v = in[i];
        uint4 u;
        u.x = f2tf32(v.x); u.y = f2tf32(v.y);
        u.z = f2tf32(v.z); u.w = f2tf32(v.w);
        out[i] = u;
    }
}

// ---------------------------------------------------------------------------
// TF32 NT GEMM, 2-stage cp.async pipeline + ldmatrix fragment loads.
// C[m,n] = sum_k A[m,k]*W[n,k] + bias[n].  BM=BN=128, BK=32, 256 thr (2x4 warps).
// ---------------------------------------------------------------------------
#define SSTR 36
#define STG_WORDS (128 * SSTR)

template <int MODE>
__global__ __launch_bounds__(256)
void gemm_tf32(const unsigned* __restrict__ A, const unsigned* __restrict__ W,
               const float* __restrict__ bias, float* __restrict__ Cout,
               int M, int N, int K)
{
    extern __shared__ unsigned sh[];
    unsigned* AsBase = sh;
    unsigned* BsBase = sh + 2 * STG_WORDS;

    const unsigned* Ap = (MODE == 1) ? (const unsigned*)g_O : A;

    int tid  = threadIdx.x;
    int lane = tid & 31;
    int wid  = tid >> 5;
    int wm = (wid >> 2) * 64;
    int wn = (wid & 3) * 32;
    int bm = blockIdx.y * 128;
    int bn = blockIdx.x * 128;
    int g = lane >> 2;
    int t = lane & 3;

    int lrow = tid >> 3;
    int lc4  = (tid & 7) * 4;

    // ldmatrix per-thread source offsets (words, within a stage)
    int lr = lane & 7;
    // A x4: tiles (r,c),(r+8,c),(r,c+4),(r+8,c+4); groups: +8row for grp 1,3; +4col grp 2,3
    int a_off = (wm + lr + (((lane >> 3) & 1) ? 8 : 0)) * SSTR + ((lane >> 4) ? 4 : 0);
    // B x4 (nt pair p): tiles (n,c),(n,c+4),(n+8,c),(n+8,c+4); +4col grp 1,3; +8row grp 2,3
    int b_off = (wn + lr + ((lane >> 4) ? 8 : 0)) * SSTR + (((lane >> 3) & 1) ? 4 : 0);

    unsigned shA = (unsigned)__cvta_generic_to_shared(AsBase);
    unsigned shB = (unsigned)__cvta_generic_to_shared(BsBase);

    float acc[4][4][4];
#pragma unroll
    for (int mt = 0; mt < 4; mt++)
#pragma unroll
        for (int nt = 0; nt < 4; nt++)
#pragma unroll
            for (int i = 0; i < 4; i++) acc[mt][nt][i] = 0.f;

    auto issue = [&](int s, int k0) {
        unsigned* dA = AsBase + s * STG_WORDS;
        unsigned* dB = BsBase + s * STG_WORDS;
#pragma unroll
        for (int r = 0; r < 4; r++) {
            int rr = lrow + r * 32;
            const unsigned* ga = Ap + (size_t)(bm + rr) * K + k0 + lc4;
            const unsigned* gb = W  + (size_t)(bn + rr) * K + k0 + lc4;
            unsigned sa = (unsigned)__cvta_generic_to_shared(&dA[rr * SSTR + lc4]);
            unsigned sb = (unsigned)__cvta_generic_to_shared(&dB[rr * SSTR + lc4]);
            asm volatile("cp.async.cg.shared.global [%0], [%1], 16;\n" :: "r"(sa), "l"(ga));
            asm volatile("cp.async.cg.shared.global [%0], [%1], 16;\n" :: "r"(sb), "l"(gb));
        }
        asm volatile("cp.async.commit_group;\n");
    };

    issue(0, 0);
    int stage = 0;

    for (int k0 = 0; k0 < K; k0 += 32) {
        bool more = (k0 + 32 < K);
        if (more) issue(stage ^ 1, k0 + 32);
        if (more) asm volatile("cp.async.wait_group 1;\n");
        else      asm volatile("cp.async.wait_group 0;\n");
        __syncthreads();

        unsigned stA = shA + stage * STG_WORDS * 4;
        unsigned stB = shB + stage * STG_WORDS * 4;

#pragma unroll
        for (int ks = 0; ks < 4; ks++) {
            int kk = ks * 8;
            unsigned af[4][4], bf[2][4];
#pragma unroll
            for (int mt = 0; mt < 4; mt++)
                ldsm_x4(af[mt], stA + (unsigned)(a_off + mt * 16 * SSTR + kk) * 4);
#pragma unroll
            for (int p = 0; p < 2; p++)
                ldsm_x4(bf[p], stB + (unsigned)(b_off + p * 16 * SSTR + kk) * 4);
#pragma unroll
            for (int mt = 0; mt < 4; mt++)
#pragma unroll
                for (int nt = 0; nt < 4; nt++)
                    mma_tf32(acc[mt][nt], af[mt], &bf[nt >> 1][(nt & 1) * 2]);
        }
        __syncthreads();
        stage ^= 1;
    }

#pragma unroll
    for (int mt = 0; mt < 4; mt++) {
#pragma unroll
        for (int nt = 0; nt < 4; nt++) {
#pragma unroll
            for (int i = 0; i < 4; i++) {
                int m = bm + wm + mt * 16 + g + ((i >> 1) ? 8 : 0);
                int n = bn + wn + nt * 8 + t * 2 + (i & 1);
                float v = acc[mt][nt][i] + bias[n];
                if (MODE == 0) {
                    int part   = n >> 10;
                    int within = n & 1023;
                    int h = within >> 6;
                    int d = within & 63;
                    int b = m >> 11;
                    int l = m & 2047;
                    size_t dst = ((size_t)(b * NHEADS + h) * SEQ + l) * HD + d;
                    float* base = (part == 0) ? g_Q : (part == 1) ? g_K : g_V;
                    base[dst] = __uint_as_float(f2tf32(v));
                } else {
                    Cout[(size_t)m * N + n] = v;
                }
            }
        }
    }
}

// ---------------------------------------------------------------------------
// Sliding-window attention, tf32 mma + ldmatrix fragments.
// One CTA = (b*h, 64-query tile), 128 threads (4 warps, warp = 16 query rows).
// ---------------------------------------------------------------------------
#define AST 68

__global__ __launch_bounds__(128)
void attn_mma()
{
    extern __shared__ unsigned smu[];
    unsigned* Qs = smu;                 // [q][d]  64 x 68
    unsigned* Ks = smu + 64 * AST;      // [j][d]
    unsigned* Vt = smu + 2 * 64 * AST;  // [d][j]
    unsigned* Ps = smu + 3 * 64 * AST;  // [q][j]

    int tid  = threadIdx.x;
    int lane = tid & 31;
    int wid  = tid >> 5;
    int g = lane >> 2;
    int t = lane & 3;
    int lr = lane & 7;

    int bh = blockIdx.y;
    int i0 = blockIdx.x * 64;

    const float* Qg = g_Q + (size_t)bh * SEQ * HD;
    const float* Kg = g_K + (size_t)bh * SEQ * HD;
    const float* Vg = g_V + (size_t)bh * SEQ * HD;

    int rbase = wid * 16;
    // A-fragment ldmatrix offsets (Q and P share the pattern; row block = rbase)
    int a_off = (rbase + lr + (((lane >> 3) & 1) ? 8 : 0)) * AST + ((lane >> 4) ? 4 : 0);
    // B-fragment x4 per nt-pair p: rows 16p + (+8 grp 2,3), col +4 grp 1,3
    int b_off = (lr + ((lane >> 4) ? 8 : 0)) * AST + (((lane >> 3) & 1) ? 4 : 0);

    unsigned shQ = (unsigned)__cvta_generic_to_shared(Qs);
    unsigned shK = (unsigned)__cvta_generic_to_shared(Ks);
    unsigned shV = (unsigned)__cvta_generic_to_shared(Vt);
    unsigned shP = (unsigned)__cvta_generic_to_shared(Ps);

    // Load Q tile, scale by 0.125 (exact exponent shift)
    {
        int q = tid >> 1, half = tid & 1;
#pragma unroll
        for (int v = 0; v < 8; v++) {
            int c4 = half * 32 + v * 4;
            float4 qv = *(const float4*)(Qg + (size_t)(i0 + q) * HD + c4);
            uint4 u;
            u.x = __float_as_uint(qv.x * 0.125f);
            u.y = __float_as_uint(qv.y * 0.125f);
            u.z = __float_as_uint(qv.z * 0.125f);
            u.w = __float_as_uint(qv.w * 0.125f);
            *(uint4*)&Qs[q * AST + c4] = u;
        }
    }

    int iq0 = i0 + rbase + g;
    int iq1 = iq0 + 8;

    float m0 = -1e30f, m1 = -1e30f, l0 = 0.f, l1 = 0.f;
    float oacc[8][4];
#pragma unroll
    for (int nt = 0; nt < 8; nt++)
#pragma unroll
        for (int i = 0; i < 4; i++) oacc[nt][i] = 0.f;

    int kv_lo = i0 - (WIN - 1);
    if (kv_lo < 0) kv_lo = 0;
    int cs0 = (kv_lo / 64) * 64;

    for (int cs = cs0; cs <= i0; cs += 64) {
        __syncthreads();
        // Stage K [j][d] and V transposed [d][j]
        {
            int j = tid >> 1, half = tid & 1;
#pragma unroll
            for (int v = 0; v < 8; v++) {
                int c4 = half * 32 + v * 4;
                *(uint4*)&Ks[j * AST + c4] =
                    *(const uint4*)(Kg + (size_t)(cs + j) * HD + c4);
                uint4 vv = *(const uint4*)(Vg + (size_t)(cs + j) * HD + c4);
                Vt[(c4 + 0) * AST + j] = vv.x;
                Vt[(c4 + 1) * AST + j] = vv.y;
                Vt[(c4 + 2) * AST + j] = vv.z;
                Vt[(c4 + 3) * AST + j] = vv.w;
            }
        }
        __syncthreads();

        // S = Q*K^T
        float sacc[8][4];
#pragma unroll
        for (int nt = 0; nt < 8; nt++)
#pragma unroll
            for (int i = 0; i < 4; i++) sacc[nt][i] = 0.f;

#pragma unroll
        for (int kk = 0; kk < 8; kk++) {
            int c = kk * 8;
            unsigned af[4], bf[4][4];
            ldsm_x4(af, shQ + (unsigned)(a_off + c) * 4);
#pragma unroll
            for (int p = 0; p < 4; p++)
                ldsm_x4(bf[p], shK + (unsigned)(b_off + p * 16 * AST + c) * 4);
#pragma unroll
            for (int nt = 0; nt < 8; nt++)
                mma_tf32(sacc[nt], af, &bf[nt >> 1][(nt & 1) * 2]);
        }

        // Mask + online softmax
        float rmax0 = -1e30f, rmax1 = -1e30f;
#pragma unroll
        for (int nt = 0; nt < 8; nt++) {
#pragma unroll
            for (int e = 0; e < 2; e++) {
                int j = cs + nt * 8 + 2 * t + e;
                if (!((j <= iq0) && (j > iq0 - WIN))) sacc[nt][e] = -1e30f;
                if (!((j <= iq1) && (j > iq1 - WIN))) sacc[nt][2 + e] = -1e30f;
                rmax0 = fmaxf(rmax0, sacc[nt][e]);
                rmax1 = fmaxf(rmax1, sacc[nt][2 + e]);
            }
        }
#pragma unroll
        for (int msk = 1; msk < 4; msk <<= 1) {
            rmax0 = fmaxf(rmax0, __shfl_xor_sync(0xffffffffu, rmax0, msk));
            rmax1 = fmaxf(rmax1, __shfl_xor_sync(0xffffffffu, rmax1, msk));
        }

        float mn0 = fmaxf(m0, rmax0);
        float mn1 = fmaxf(m1, rmax1);
        float cor0 = __expf(m0 - mn0);
        float cor1 = __expf(m1 - mn1);
        m0 = mn0; m1 = mn1;

        float rs0 = 0.f, rs1 = 0.f;
#pragma unroll
        for (int nt = 0; nt < 8; nt++) {
            float p0 = __expf(sacc[nt][0] - mn0);
            float p1 = __expf(sacc[nt][1] - mn0);
            float p2 = __expf(sacc[nt][2] - mn1);
            float p3 = __expf(sacc[nt][3] - mn1);
            rs0 += p0 + p1;
            rs1 += p2 + p3;
            int col = nt * 8 + 2 * t;
            uint2 u0 = { f2tf32(p0), f2tf32(p1) };
            uint2 u1 = { f2tf32(p2), f2tf32(p3) };
            *(uint2*)&Ps[(rbase + g) * AST + col]     = u0;
            *(uint2*)&Ps[(rbase + g + 8) * AST + col] = u1;
        }
#pragma unroll
        for (int msk = 1; msk < 4; msk <<= 1) {
            rs0 += __shfl_xor_sync(0xffffffffu, rs0, msk);
            rs1 += __shfl_xor_sync(0xffffffffu, rs1, msk);
        }
        l0 = l0 * cor0 + rs0;
        l1 = l1 * cor1 + rs1;
#pragma unroll
        for (int nt = 0; nt < 8; nt++) {
            oacc[nt][0] *= cor0; oacc[nt][1] *= cor0;
            oacc[nt][2] *= cor1; oacc[nt][3] *= cor1;
        }
        __syncwarp();

        // O += P * V
#pragma unroll
        for (int kk = 0; kk < 8; kk++) {
            int c = kk * 8;
            unsigned af[4], bf[4][4];
            ldsm_x4(af, shP + (unsigned)(a_off + c) * 4);
#pragma unroll
            for (int p = 0; p < 4; p++)
                ldsm_x4(bf[p], shV + (unsigned)(b_off + p * 16 * AST + c) * 4);
#pragma unroll
            for (int nt = 0; nt < 8; nt++)
                mma_tf32(oacc[nt], af, &bf[nt >> 1][(nt & 1) * 2]);
        }
    }

    // Normalize + write tf32-rounded O
    float inv0 = 1.f / l0;
    float inv1 = 1.f / l1;
    int b = bh / NHEADS;
    int h = bh % NHEADS;
    float* O0 = g_O + (size_t)(b * SEQ + iq0) * D_MODEL + h * HD;
    float* O1 = g_O + (size_t)(b * SEQ + iq1) * D_MODEL + h * HD;
#pragma unroll
    for (int nt = 0; nt < 8; nt++) {
        int d = nt * 8 + 2 * t;
        uint2 v0 = { f2tf32(oacc[nt][0] * inv0), f2tf32(oacc[nt][1] * inv0) };
        uint2 v1 = { f2tf32(oacc[nt][2] * inv1), f2tf32(oacc[nt][3] * inv1) };
        *(uint2*)(O0 + d) = *(uint2*)&v0;
        *(uint2*)(O1 + d) = *(uint2*)&v1;
    }
}

// ---------------------------------------------------------------------------
extern "C" void kernel_launch(void* const* d_in, const int* in_sizes, int n_in,
                              void* d_out, int out_size)
{
    const float* x  = (const float*)d_in[0];
    const float* w1 = (const float*)d_in[1];
    const float* b1 = (const float*)d_in[2];
    const float* w2 = (const float*)d_in[3];
    const float* b2 = (const float*)d_in[4];
    float* out = (float*)d_out;

    const int M = BATCH * SEQ;

    unsigned *cx, *cw1, *cw2;
    cudaGetSymbolAddress((void**)&cx,  c_x);
    cudaGetSymbolAddress((void**)&cw1, c_w1);
    cudaGetSymbolAddress((void**)&cw2, c_w2);

    {
        int n4x = M * D_MODEL / 4;
        cvt_tf32<<<(n4x + 255) / 256, 256>>>((const float4*)x, (uint4*)cx, n4x);
        int n4w1 = 3 * D_MODEL * D_MODEL / 4;
        cvt_tf32<<<(n4w1 + 255) / 256, 256>>>((const float4*)w1, (uint4*)cw1, n4w1);
        int n4w2 = D_MODEL * D_MODEL / 4;
        cvt_tf32<<<(n4w2 + 255) / 256, 256>>>((const float4*)w2, (uint4*)cw2, n4w2);
    }

    const int gemm_smem = 4 * STG_WORDS * sizeof(unsigned);   // 73728 B

    {
        cudaFuncSetAttribute(gemm_tf32<0>,
                             cudaFuncAttributeMaxDynamicSharedMemorySize, gemm_smem);
        dim3 grid(3 * D_MODEL / 128, M / 128);
        gemm_tf32<0><<<grid, 256, gemm_smem>>>(cx, cw1, b1, nullptr, M, 3 * D_MODEL, D_MODEL);
    }

    {
        int smem = 4 * 64 * AST * sizeof(unsigned);  // 69632 B
        cudaFuncSetAttribute(attn_mma,
                             cudaFuncAttributeMaxDynamicSharedMemorySize, smem);
        dim3 grid(SEQ / 64, BATCH * NHEADS);
        attn_mma<<<grid, 128, smem>>>();
    }

    {
        cudaFuncSetAttribute(gemm_tf32<1>,
                             cudaFuncAttributeMaxDynamicSharedMemorySize, gemm_smem);
        dim3 grid(D_MODEL / 128, M / 128);
        gemm_tf32<1><<<grid, 256, gemm_smem>>>(nullptr, cw2, b2, out, M, D_MODEL, D_MODEL);
    }
}

// round 7
// speedup vs baseline: 1.0729x; 1.0246x over previous
#include <cuda_runtime.h>
#include <math.h>
#include <stdint.h>

#define D_MODEL 1024
#define NHEADS  16
#define HD      64
#define SEQ     2048
#define BATCH   2
#define WIN     256

// Scratch (allocation-free: __device__ globals). All tf32-rounded bit patterns.
__device__ float g_Q[BATCH * NHEADS * SEQ * HD];   // [b][h][l][d]
__device__ float g_K[BATCH * NHEADS * SEQ * HD];
__device__ float g_V[BATCH * NHEADS * SEQ * HD];
__device__ float g_O[BATCH * SEQ * D_MODEL];       // [b][l][h*64+d]
__device__ unsigned c_x [BATCH * SEQ * D_MODEL];
__device__ unsigned c_w1[3 * D_MODEL * D_MODEL];
__device__ unsigned c_w2[D_MODEL * D_MODEL];

__device__ __forceinline__ unsigned f2tf32(float f) {
    unsigned r;
    asm("cvt.rna.tf32.f32 %0, %1;" : "=r"(r) : "f"(f));
    return r;
}

__device__ __forceinline__ void mma_tf32(float c[4], const unsigned a[4], const unsigned b[2]) {
    asm volatile(
        "mma.sync.aligned.m16n8k8.row.col.f32.tf32.tf32.f32 "
        "{%0,%1,%2,%3}, {%4,%5,%6,%7}, {%8,%9}, {%0,%1,%2,%3};\n"
        : "+f"(c[0]), "+f"(c[1]), "+f"(c[2]), "+f"(c[3])
        : "r"(a[0]), "r"(a[1]), "r"(a[2]), "r"(a[3]),
          "r"(b[0]), "r"(b[1]));
}

__device__ __forceinline__ void ldsm_x4(unsigned a[4], unsigned saddr) {
    asm volatile("ldmatrix.sync.aligned.m8n8.x4.shared.b16 {%0,%1,%2,%3}, [%4];"
        : "=r"(a[0]), "=r"(a[1]), "=r"(a[2]), "=r"(a[3]) : "r"(saddr));
}

// ---------------------------------------------------------------------------
// fp32 -> tf32 bulk converter
// ---------------------------------------------------------------------------
__global__ void cvt_tf32(const float4* __restrict__ in, uint4* __restrict__ out, int n4)
{
    int i = blockIdx.x * blockDim.x + threadIdx.x;
    if (i < n4) {
        float4 v = in[i];
        uint4 u;
        u.x = f2tf32(v.x); u.y = f2tf32(v.y);
        u.z = f2tf32(v.z); u.w = f2tf32(v.w);
        out[i] = u;
    }
}

// ---------------------------------------------------------------------------
// TF32 NT GEMM, 3-stage cp.async pipeline (ONE barrier per k-tile) + ldmatrix.
// C[m,n] = sum_k A[m,k]*W[n,k] + bias[n].  BM=BN=128, BK=32, 256 thr (2x4 warps).
// ---------------------------------------------------------------------------
#define SSTR 36
#define STG_WORDS (128 * SSTR)
#define NSTG 3

template <int MODE>
__global__ __launch_bounds__(256)
void gemm_tf32(const unsigned* __restrict__ A, const unsigned* __restrict__ W,
               const float* __restrict__ bias, float* __restrict__ Cout,
               int M, int N, int K)
{
    extern __shared__ unsigned sh[];
    unsigned* AsBase = sh;                       // NSTG stages of A
    unsigned* BsBase = sh + NSTG * STG_WORDS;    // NSTG stages of B

    const unsigned* Ap = (MODE == 1) ? (const unsigned*)g_O : A;

    int tid  = threadIdx.x;
    int lane = tid & 31;
    int wid  = tid >> 5;
    int wm = (wid >> 2) * 64;
    int wn = (wid & 3) * 32;
    int bm = blockIdx.y * 128;
    int bn = blockIdx.x * 128;
    int g = lane >> 2;
    int t = lane & 3;

    int lrow = tid >> 3;
    int lc4  = (tid & 7) * 4;

    int lr = lane & 7;
    int a_off = (wm + lr + (((lane >> 3) & 1) ? 8 : 0)) * SSTR + ((lane >> 4) ? 4 : 0);
    int b_off = (wn + lr + ((lane >> 4) ? 8 : 0)) * SSTR + (((lane >> 3) & 1) ? 4 : 0);

    unsigned shA = (unsigned)__cvta_generic_to_shared(AsBase);
    unsigned shB = (unsigned)__cvta_generic_to_shared(BsBase);

    float acc[4][4][4];
#pragma unroll
    for (int mt = 0; mt < 4; mt++)
#pragma unroll
        for (int nt = 0; nt < 4; nt++)
#pragma unroll
            for (int i = 0; i < 4; i++) acc[mt][nt][i] = 0.f;

    auto issue = [&](int s, int k0) {
        unsigned* dA = AsBase + s * STG_WORDS;
        unsigned* dB = BsBase + s * STG_WORDS;
#pragma unroll
        for (int r = 0; r < 4; r++) {
            int rr = lrow + r * 32;
            const unsigned* ga = Ap + (size_t)(bm + rr) * K + k0 + lc4;
            const unsigned* gb = W  + (size_t)(bn + rr) * K + k0 + lc4;
            unsigned sa = (unsigned)__cvta_generic_to_shared(&dA[rr * SSTR + lc4]);
            unsigned sb = (unsigned)__cvta_generic_to_shared(&dB[rr * SSTR + lc4]);
            asm volatile("cp.async.cg.shared.global [%0], [%1], 16;\n" :: "r"(sa), "l"(ga));
            asm volatile("cp.async.cg.shared.global [%0], [%1], 16;\n" :: "r"(sb), "l"(gb));
        }
        asm volatile("cp.async.commit_group;\n");
    };

    const int TILES = K / 32;
    issue(0, 0);
    issue(1, 32);

    int stage = 0;             // stage holding tile t
    int fill  = 2;             // next stage to fill (= (t-1)%3 at iter t>=1... rotates)

    for (int t2 = 0; t2 < TILES; t2++) {
        // tile t2 data complete (tile t2+1 may still be in flight)
        asm volatile("cp.async.wait_group 1;\n" ::: "memory");
        // One barrier: (a) all warps see tile t2's data; (b) all warps finished
        // reading the 'fill' stage during iteration t2-1 -> safe to overwrite.
        __syncthreads();

        if (t2 + 2 < TILES) issue(fill, (t2 + 2) * 32);

        unsigned stA = shA + stage * (STG_WORDS * 4);
        unsigned stB = shB + stage * (STG_WORDS * 4);

#pragma unroll
        for (int ks = 0; ks < 4; ks++) {
            int kk = ks * 8;
            unsigned af[4][4], bf[2][4];
#pragma unroll
            for (int mt = 0; mt < 4; mt++)
                ldsm_x4(af[mt], stA + (unsigned)(a_off + mt * 16 * SSTR + kk) * 4);
#pragma unroll
            for (int p = 0; p < 2; p++)
                ldsm_x4(bf[p], stB + (unsigned)(b_off + p * 16 * SSTR + kk) * 4);
#pragma unroll
            for (int mt = 0; mt < 4; mt++)
#pragma unroll
                for (int nt = 0; nt < 4; nt++)
                    mma_tf32(acc[mt][nt], af[mt], &bf[nt >> 1][(nt & 1) * 2]);
        }

        fill  = stage;                       // current stage becomes refill target next iter
        stage = (stage == 2) ? 0 : stage + 1;
    }

#pragma unroll
    for (int mt = 0; mt < 4; mt++) {
#pragma unroll
        for (int nt = 0; nt < 4; nt++) {
#pragma unroll
            for (int i = 0; i < 4; i++) {
                int m = bm + wm + mt * 16 + g + ((i >> 1) ? 8 : 0);
                int n = bn + wn + nt * 8 + t * 2 + (i & 1);
                float v = acc[mt][nt][i] + bias[n];
                if (MODE == 0) {
                    int part   = n >> 10;
                    int within = n & 1023;
                    int h = within >> 6;
                    int d = within & 63;
                    int b = m >> 11;
                    int l = m & 2047;
                    size_t dst = ((size_t)(b * NHEADS + h) * SEQ + l) * HD + d;
                    float* base = (part == 0) ? g_Q : (part == 1) ? g_K : g_V;
                    base[dst] = __uint_as_float(f2tf32(v));
                } else {
                    Cout[(size_t)m * N + n] = v;
                }
            }
        }
    }
}

// ---------------------------------------------------------------------------
// Sliding-window attention, tf32 mma.sync + ldmatrix (unchanged from R5).
// ---------------------------------------------------------------------------
#define AST 68

__global__ __launch_bounds__(128)
void attn_mma()
{
    extern __shared__ unsigned smu[];
    unsigned* Qs = smu;                 // [q][d]  64 x 68
    unsigned* Ks = smu + 64 * AST;      // [j][d]
    unsigned* Vt = smu + 2 * 64 * AST;  // [d][j]
    unsigned* Ps = smu + 3 * 64 * AST;  // [q][j]

    int tid  = threadIdx.x;
    int lane = tid & 31;
    int wid  = tid >> 5;
    int g = lane >> 2;
    int t = lane & 3;
    int lr = lane & 7;

    int bh = blockIdx.y;
    int i0 = blockIdx.x * 64;

    const float* Qg = g_Q + (size_t)bh * SEQ * HD;
    const float* Kg = g_K + (size_t)bh * SEQ * HD;
    const float* Vg = g_V + (size_t)bh * SEQ * HD;

    int rbase = wid * 16;
    int a_off = (rbase + lr + (((lane >> 3) & 1) ? 8 : 0)) * AST + ((lane >> 4) ? 4 : 0);
    int b_off = (lr + ((lane >> 4) ? 8 : 0)) * AST + (((lane >> 3) & 1) ? 4 : 0);

    unsigned shQ = (unsigned)__cvta_generic_to_shared(Qs);
    unsigned shK = (unsigned)__cvta_generic_to_shared(Ks);
    unsigned shV = (unsigned)__cvta_generic_to_shared(Vt);
    unsigned shP = (unsigned)__cvta_generic_to_shared(Ps);

    {
        int q = tid >> 1, half = tid & 1;
#pragma unroll
        for (int v = 0; v < 8; v++) {
            int c4 = half * 32 + v * 4;
            float4 qv = *(const float4*)(Qg + (size_t)(i0 + q) * HD + c4);
            uint4 u;
            u.x = __float_as_uint(qv.x * 0.125f);
            u.y = __float_as_uint(qv.y * 0.125f);
            u.z = __float_as_uint(qv.z * 0.125f);
            u.w = __float_as_uint(qv.w * 0.125f);
            *(uint4*)&Qs[q * AST + c4] = u;
        }
    }

    int iq0 = i0 + rbase + g;
    int iq1 = iq0 + 8;

    float m0 = -1e30f, m1 = -1e30f, l0 = 0.f, l1 = 0.f;
    float oacc[8][4];
#pragma unroll
    for (int nt = 0; nt < 8; nt++)
#pragma unroll
        for (int i = 0; i < 4; i++) oacc[nt][i] = 0.f;

    int kv_lo = i0 - (WIN - 1);
    if (kv_lo < 0) kv_lo = 0;
    int cs0 = (kv_lo / 64) * 64;

    for (int cs = cs0; cs <= i0; cs += 64) {
        __syncthreads();
        {
            int j = tid >> 1, half = tid & 1;
#pragma unroll
            for (int v = 0; v < 8; v++) {
                int c4 = half * 32 + v * 4;
                *(uint4*)&Ks[j * AST + c4] =
                    *(const uint4*)(Kg + (size_t)(cs + j) * HD + c4);
                uint4 vv = *(const uint4*)(Vg + (size_t)(cs + j) * HD + c4);
                Vt[(c4 + 0) * AST + j] = vv.x;
                Vt[(c4 + 1) * AST + j] = vv.y;
                Vt[(c4 + 2) * AST + j] = vv.z;
                Vt[(c4 + 3) * AST + j] = vv.w;
            }
        }
        __syncthreads();

        float sacc[8][4];
#pragma unroll
        for (int nt = 0; nt < 8; nt++)
#pragma unroll
            for (int i = 0; i < 4; i++) sacc[nt][i] = 0.f;

#pragma unroll
        for (int kk = 0; kk < 8; kk++) {
            int c = kk * 8;
            unsigned af[4], bf[4][4];
            ldsm_x4(af, shQ + (unsigned)(a_off + c) * 4);
#pragma unroll
            for (int p = 0; p < 4; p++)
                ldsm_x4(bf[p], shK + (unsigned)(b_off + p * 16 * AST + c) * 4);
#pragma unroll
            for (int nt = 0; nt < 8; nt++)
                mma_tf32(sacc[nt], af, &bf[nt >> 1][(nt & 1) * 2]);
        }

        float rmax0 = -1e30f, rmax1 = -1e30f;
#pragma unroll
        for (int nt = 0; nt < 8; nt++) {
#pragma unroll
            for (int e = 0; e < 2; e++) {
                int j = cs + nt * 8 + 2 * t + e;
                if (!((j <= iq0) && (j > iq0 - WIN))) sacc[nt][e] = -1e30f;
                if (!((j <= iq1) && (j > iq1 - WIN))) sacc[nt][2 + e] = -1e30f;
                rmax0 = fmaxf(rmax0, sacc[nt][e]);
                rmax1 = fmaxf(rmax1, sacc[nt][2 + e]);
            }
        }
#pragma unroll
        for (int msk = 1; msk < 4; msk <<= 1) {
            rmax0 = fmaxf(rmax0, __shfl_xor_sync(0xffffffffu, rmax0, msk));
            rmax1 = fmaxf(rmax1, __shfl_xor_sync(0xffffffffu, rmax1, msk));
        }

        float mn0 = fmaxf(m0, rmax0);
        float mn1 = fmaxf(m1, rmax1);
        float cor0 = __expf(m0 - mn0);
        float cor1 = __expf(m1 - mn1);
        m0 = mn0; m1 = mn1;

        float rs0 = 0.f, rs1 = 0.f;
#pragma unroll
        for (int nt = 0; nt < 8; nt++) {
            float p0 = __expf(sacc[nt][0] - mn0);
            float p1 = __expf(sacc[nt][1] - mn0);
            float p2 = __expf(sacc[nt][2] - mn1);
            float p3 = __expf(sacc[nt][3] - mn1);
            rs0 += p0 + p1;
            rs1 += p2 + p3;
            int col = nt * 8 + 2 * t;
            uint2 u0 = { f2tf32(p0), f2tf32(p1) };
            uint2 u1 = { f2tf32(p2), f2tf32(p3) };
            *(uint2*)&Ps[(rbase + g) * AST + col]     = u0;
            *(uint2*)&Ps[(rbase + g + 8) * AST + col] = u1;
        }
#pragma unroll
        for (int msk = 1; msk < 4; msk <<= 1) {
            rs0 += __shfl_xor_sync(0xffffffffu, rs0, msk);
            rs1 += __shfl_xor_sync(0xffffffffu, rs1, msk);
        }
        l0 = l0 * cor0 + rs0;
        l1 = l1 * cor1 + rs1;
#pragma unroll
        for (int nt = 0; nt < 8; nt++) {
            oacc[nt][0] *= cor0; oacc[nt][1] *= cor0;
            oacc[nt][2] *= cor1; oacc[nt][3] *= cor1;
        }
        __syncwarp();

#pragma unroll
        for (int kk = 0; kk < 8; kk++) {
            int c = kk * 8;
            unsigned af[4], bf[4][4];
            ldsm_x4(af, shP + (unsigned)(a_off + c) * 4);
#pragma unroll
            for (int p = 0; p < 4; p++)
                ldsm_x4(bf[p], shV + (unsigned)(b_off + p * 16 * AST + c) * 4);
#pragma unroll
            for (int nt = 0; nt < 8; nt++)
                mma_tf32(oacc[nt], af, &bf[nt >> 1][(nt & 1) * 2]);
        }
    }

    float inv0 = 1.f / l0;
    float inv1 = 1.f / l1;
    int b = bh / NHEADS;
    int h = bh % NHEADS;
    float* O0 = g_O + (size_t)(b * SEQ + iq0) * D_MODEL + h * HD;
    float* O1 = g_O + (size_t)(b * SEQ + iq1) * D_MODEL + h * HD;
#pragma unroll
    for (int nt = 0; nt < 8; nt++) {
        int d = nt * 8 + 2 * t;
        uint2 v0 = { f2tf32(oacc[nt][0] * inv0), f2tf32(oacc[nt][1] * inv0) };
        uint2 v1 = { f2tf32(oacc[nt][2] * inv1), f2tf32(oacc[nt][3] * inv1) };
        *(uint2*)(O0 + d) = *(uint2*)&v0;
        *(uint2*)(O1 + d) = *(uint2*)&v1;
    }
}

// ---------------------------------------------------------------------------
extern "C" void kernel_launch(void* const* d_in, const int* in_sizes, int n_in,
                              void* d_out, int out_size)
{
    const float* x  = (const float*)d_in[0];
    const float* w1 = (const float*)d_in[1];
    const float* b1 = (const float*)d_in[2];
    const float* w2 = (const float*)d_in[3];
    const float* b2 = (const float*)d_in[4];
    float* out = (float*)d_out;

    const int M = BATCH * SEQ;

    unsigned *cx, *cw1, *cw2;
    cudaGetSymbolAddress((void**)&cx,  c_x);
    cudaGetSymbolAddress((void**)&cw1, c_w1);
    cudaGetSymbolAddress((void**)&cw2, c_w2);

    {
        int n4x = M * D_MODEL / 4;
        cvt_tf32<<<(n4x + 255) / 256, 256>>>((const float4*)x, (uint4*)cx, n4x);
        int n4w1 = 3 * D_MODEL * D_MODEL / 4;
        cvt_tf32<<<(n4w1 + 255) / 256, 256>>>((const float4*)w1, (uint4*)cw1, n4w1);
        int n4w2 = D_MODEL * D_MODEL / 4;
        cvt_tf32<<<(n4w2 + 255) / 256, 256>>>((const float4*)w2, (uint4*)cw2, n4w2);
    }

    const int gemm_smem = 2 * NSTG * STG_WORDS * sizeof(unsigned);   // 110592 B

    {
        cudaFuncSetAttribute(gemm_tf32<0>,
                             cudaFuncAttributeMaxDynamicSharedMemorySize, gemm_smem);
        dim3 grid(3 * D_MODEL / 128, M / 128);
        gemm_tf32<0><<<grid, 256, gemm_smem>>>(cx, cw1, b1, nullptr, M, 3 * D_MODEL, D_MODEL);
    }

    {
        int smem = 4 * 64 * AST * sizeof(unsigned);  // 69632 B
        cudaFuncSetAttribute(attn_mma,
                             cudaFuncAttributeMaxDynamicSharedMemorySize, smem);
        dim3 grid(SEQ / 64, BATCH * NHEADS);
        attn_mma<<<grid, 128, smem>>>();
    }

    {
        cudaFuncSetAttribute(gemm_tf32<1>,
                             cudaFuncAttributeMaxDynamicSharedMemorySize, gemm_smem);
        dim3 grid(D_MODEL / 128, M / 128);
        gemm_tf32<1><<<grid, 256, gemm_smem>>>(nullptr, cw2, b2, out, M, D_MODEL, D_MODEL);
    }
}

// round 8
// speedup vs baseline: 1.8117x; 1.6886x over previous
#include <cuda_runtime.h>
#include <cuda_fp16.h>
#include <math.h>
#include <stdint.h>

#define D_MODEL 1024
#define NHEADS  16
#define HD      64
#define SEQ     2048
#define BATCH   2
#define WIN     256

// Scratch (allocation-free: __device__ globals). All fp16.
__device__ __half g_Q[BATCH * NHEADS * SEQ * HD];   // [b][h][l][d]
__device__ __half g_K[BATCH * NHEADS * SEQ * HD];
__device__ __half g_V[BATCH * NHEADS * SEQ * HD];
__device__ __half g_O[BATCH * SEQ * D_MODEL];       // [b][l][h*64+d]
__device__ __half c_x [BATCH * SEQ * D_MODEL];
__device__ __half c_w1[3 * D_MODEL * D_MODEL];
__device__ __half c_w2[D_MODEL * D_MODEL];

__device__ __forceinline__ void mma_f16(float c[4], const unsigned a[4], const unsigned b[2]) {
    asm volatile(
        "mma.sync.aligned.m16n8k16.row.col.f32.f16.f16.f32 "
        "{%0,%1,%2,%3}, {%4,%5,%6,%7}, {%8,%9}, {%0,%1,%2,%3};\n"
        : "+f"(c[0]), "+f"(c[1]), "+f"(c[2]), "+f"(c[3])
        : "r"(a[0]), "r"(a[1]), "r"(a[2]), "r"(a[3]),
          "r"(b[0]), "r"(b[1]));
}

__device__ __forceinline__ void ldsm_x4(unsigned a[4], unsigned saddr) {
    asm volatile("ldmatrix.sync.aligned.m8n8.x4.shared.b16 {%0,%1,%2,%3}, [%4];"
        : "=r"(a[0]), "=r"(a[1]), "=r"(a[2]), "=r"(a[3]) : "r"(saddr));
}

// ---------------------------------------------------------------------------
// fp32 -> fp16 bulk converter (float4 -> 4 halves)
// ---------------------------------------------------------------------------
__global__ void cvt_f16(const float4* __restrict__ in, uint2* __restrict__ out, int n4)
{
    int i = blockIdx.x * blockDim.x + threadIdx.x;
    if (i < n4) {
        float4 v = in[i];
        __half2 h01 = __floats2half2_rn(v.x, v.y);
        __half2 h23 = __floats2half2_rn(v.z, v.w);
        uint2 u;
        u.x = *(unsigned*)&h01;
        u.y = *(unsigned*)&h23;
        out[i] = u;
    }
}

// ---------------------------------------------------------------------------
// FP16 NT GEMM (fp32 accum), 3-stage cp.async pipeline + ldmatrix.
// C[m,n] = sum_k A[m,k]*W[n,k] + bias[n].  BM=BN=128, BK=32, 256 thr (2x4 warps).
// Smem rows: 32 halves data, stride SSTR=40 halves (80B) -> LDSM conflict-free.
// ---------------------------------------------------------------------------
#define SSTR 40
#define STG_HALVES (128 * SSTR)             // per A (or B) stage
#define STG_BYTES  (STG_HALVES * 2)         // 10240
#define NSTG 3

template <int MODE>
__global__ __launch_bounds__(256)
void gemm_f16(const __half* __restrict__ A, const __half* __restrict__ W,
              const float* __restrict__ bias, float* __restrict__ Cout,
              int M, int N, int K)
{
    extern __shared__ __half sh[];
    __half* AsBase = sh;                        // NSTG stages of A
    __half* BsBase = sh + NSTG * STG_HALVES;    // NSTG stages of B

    const __half* Ap = (MODE == 1) ? (const __half*)g_O : A;

    int tid  = threadIdx.x;
    int lane = tid & 31;
    int wid  = tid >> 5;
    int wm = (wid >> 2) * 64;
    int wn = (wid & 3) * 32;
    int bm = blockIdx.y * 128;
    int bn = blockIdx.x * 128;
    int g = lane >> 2;
    int t = lane & 3;
    int lr = lane & 7;

    // ldmatrix source offsets (in halves)
    // A x4 tiles: (r,kk),(r+8,kk),(r,kk+8),(r+8,kk+8)
    int a_off = (wm + lr + (((lane >> 3) & 1) ? 8 : 0)) * SSTR + ((lane >> 4) ? 8 : 0);
    // B x4 tiles for nt-pair p: (n,kk),(n,kk+8),(n+8,kk),(n+8,kk+8)
    int b_off = (wn + lr + ((lane >> 4) ? 8 : 0)) * SSTR + (((lane >> 3) & 1) ? 8 : 0);

    unsigned shA = (unsigned)__cvta_generic_to_shared(AsBase);
    unsigned shB = (unsigned)__cvta_generic_to_shared(BsBase);

    float acc[4][4][4];
#pragma unroll
    for (int mt = 0; mt < 4; mt++)
#pragma unroll
        for (int nt = 0; nt < 4; nt++)
#pragma unroll
            for (int i = 0; i < 4; i++) acc[mt][nt][i] = 0.f;

    // 128 rows x 64B per operand per stage -> 512 chunks of 16B each; 2 A + 2 B per thread
    int lrow = tid >> 2;          // 0..63
    int lc   = tid & 3;           // 16B chunk within row
    auto issue = [&](int s, int k0) {
        __half* dA = AsBase + s * STG_HALVES;
        __half* dB = BsBase + s * STG_HALVES;
#pragma unroll
        for (int r = 0; r < 2; r++) {
            int rr = lrow + r * 64;
            const __half* ga = Ap + (size_t)(bm + rr) * K + k0 + lc * 8;
            const __half* gb = W  + (size_t)(bn + rr) * K + k0 + lc * 8;
            unsigned sa = (unsigned)__cvta_generic_to_shared(dA + rr * SSTR + lc * 8);
            unsigned sb = (unsigned)__cvta_generic_to_shared(dB + rr * SSTR + lc * 8);
            asm volatile("cp.async.cg.shared.global [%0], [%1], 16;\n" :: "r"(sa), "l"(ga));
            asm volatile("cp.async.cg.shared.global [%0], [%1], 16;\n" :: "r"(sb), "l"(gb));
        }
        asm volatile("cp.async.commit_group;\n");
    };

    const int TILES = K / 32;
    issue(0, 0);
    issue(1, 32);

    int stage = 0, fill = 2;

    for (int t2 = 0; t2 < TILES; t2++) {
        asm volatile("cp.async.wait_group 1;\n" ::: "memory");
        __syncthreads();

        if (t2 + 2 < TILES) issue(fill, (t2 + 2) * 32);

        unsigned stA = shA + stage * STG_BYTES;
        unsigned stB = shB + stage * STG_BYTES;

#pragma unroll
        for (int ks = 0; ks < 2; ks++) {
            int kk = ks * 16;
            unsigned af[4][4], bf[2][4];
#pragma unroll
            for (int mt = 0; mt < 4; mt++)
                ldsm_x4(af[mt], stA + (unsigned)(a_off + mt * 16 * SSTR + kk) * 2);
#pragma unroll
            for (int p = 0; p < 2; p++)
                ldsm_x4(bf[p], stB + (unsigned)(b_off + p * 16 * SSTR + kk) * 2);
#pragma unroll
            for (int mt = 0; mt < 4; mt++)
#pragma unroll
                for (int nt = 0; nt < 4; nt++)
                    mma_f16(acc[mt][nt], af[mt], &bf[nt >> 1][(nt & 1) * 2]);
        }

        fill  = stage;
        stage = (stage == 2) ? 0 : stage + 1;
    }

#pragma unroll
    for (int mt = 0; mt < 4; mt++) {
#pragma unroll
        for (int nt = 0; nt < 4; nt++) {
#pragma unroll
            for (int i = 0; i < 4; i++) {
                int m = bm + wm + mt * 16 + g + ((i >> 1) ? 8 : 0);
                int n = bn + wn + nt * 8 + t * 2 + (i & 1);
                float v = acc[mt][nt][i] + bias[n];
                if (MODE == 0) {
                    int part   = n >> 10;
                    int within = n & 1023;
                    int h = within >> 6;
                    int d = within & 63;
                    int b = m >> 11;
                    int l = m & 2047;
                    size_t dst = ((size_t)(b * NHEADS + h) * SEQ + l) * HD + d;
                    __half* base = (part == 0) ? g_Q : (part == 1) ? g_K : g_V;
                    base[dst] = __float2half_rn(v);
                } else {
                    Cout[(size_t)m * N + n] = v;
                }
            }
        }
    }
}

// ---------------------------------------------------------------------------
// Sliding-window attention, fp16 mma (fp32 accum/softmax) + ldmatrix.
// One CTA = (b*h, 64-query tile), 128 threads (4 warps, warp = 16 query rows).
// Smem row stride AST=72 halves (144B) -> LDSM conflict-free.
// ---------------------------------------------------------------------------
#define AST 72

__global__ __launch_bounds__(128)
void attn_mma()
{
    extern __shared__ __half smh[];
    __half* Qs = smh;                 // [q][d]  64 x AST
    __half* Ks = smh + 64 * AST;      // [j][d]
    __half* Vt = smh + 2 * 64 * AST;  // [d][j]
    __half* Ps = smh + 3 * 64 * AST;  // [q][j]

    int tid  = threadIdx.x;
    int lane = tid & 31;
    int wid  = tid >> 5;
    int g = lane >> 2;
    int t = lane & 3;
    int lr = lane & 7;

    int bh = blockIdx.y;
    int i0 = blockIdx.x * 64;

    const __half* Qg = g_Q + (size_t)bh * SEQ * HD;
    const __half* Kg = g_K + (size_t)bh * SEQ * HD;
    const __half* Vg = g_V + (size_t)bh * SEQ * HD;

    int rbase = wid * 16;
    int a_off = (rbase + lr + (((lane >> 3) & 1) ? 8 : 0)) * AST + ((lane >> 4) ? 8 : 0);
    int b_off = (lr + ((lane >> 4) ? 8 : 0)) * AST + (((lane >> 3) & 1) ? 8 : 0);

    unsigned shQ = (unsigned)__cvta_generic_to_shared(Qs);
    unsigned shK = (unsigned)__cvta_generic_to_shared(Ks);
    unsigned shV = (unsigned)__cvta_generic_to_shared(Vt);
    unsigned shP = (unsigned)__cvta_generic_to_shared(Ps);

    // Load Q tile scaled by 0.125 (exact in fp16: exponent shift)
    {
        int q = tid >> 1, half_sel = tid & 1;
        const __half2 s2 = __floats2half2_rn(0.125f, 0.125f);
#pragma unroll
        for (int v = 0; v < 4; v++) {
            int c8 = half_sel * 32 + v * 8;
            uint2 raw = *(const uint2*)(Qg + (size_t)(i0 + q) * HD + c8);
            __half2 h0 = __hmul2(*(__half2*)&raw.x, s2);
            __half2 h1 = __hmul2(*(__half2*)&raw.y, s2);
            uint2 raw2 = *(const uint2*)(Qg + (size_t)(i0 + q) * HD + c8 + 4);
            __half2 h2 = __hmul2(*(__half2*)&raw2.x, s2);
            __half2 h3 = __hmul2(*(__half2*)&raw2.y, s2);
            __half* dst = Qs + q * AST + c8;
            *(__half2*)(dst)     = h0;
            *(__half2*)(dst + 2) = h1;
            *(__half2*)(dst + 4) = h2;
            *(__half2*)(dst + 6) = h3;
        }
    }

    int iq0 = i0 + rbase + g;
    int iq1 = iq0 + 8;

    float m0 = -1e30f, m1 = -1e30f, l0 = 0.f, l1 = 0.f;
    float oacc[8][4];
#pragma unroll
    for (int nt = 0; nt < 8; nt++)
#pragma unroll
        for (int i = 0; i < 4; i++) oacc[nt][i] = 0.f;

    int kv_lo = i0 - (WIN - 1);
    if (kv_lo < 0) kv_lo = 0;
    int cs0 = (kv_lo / 64) * 64;

    for (int cs = cs0; cs <= i0; cs += 64) {
        __syncthreads();
        // Stage K [j][d] and V transposed [d][j]
        {
            int j = tid >> 1, half_sel = tid & 1;
#pragma unroll
            for (int v = 0; v < 2; v++) {
                int c16 = half_sel * 32 + v * 16;   // 16 halves per uint4x2
                uint4 kraw = *(const uint4*)(Kg + (size_t)(cs + j) * HD + c16);
                *(uint4*)(Ks + j * AST + c16) = kraw;
                uint4 kraw2 = *(const uint4*)(Kg + (size_t)(cs + j) * HD + c16 + 8);
                *(uint4*)(Ks + j * AST + c16 + 8) = kraw2;

                uint4 vraw = *(const uint4*)(Vg + (size_t)(cs + j) * HD + c16);
                const __half* vh = (const __half*)&vraw;
#pragma unroll
                for (int e = 0; e < 8; e++)
                    Vt[(c16 + e) * AST + j] = vh[e];
                uint4 vraw2 = *(const uint4*)(Vg + (size_t)(cs + j) * HD + c16 + 8);
                const __half* vh2 = (const __half*)&vraw2;
#pragma unroll
                for (int e = 0; e < 8; e++)
                    Vt[(c16 + 8 + e) * AST + j] = vh2[e];
            }
        }
        __syncthreads();

        // S = Q*K^T
        float sacc[8][4];
#pragma unroll
        for (int nt = 0; nt < 8; nt++)
#pragma unroll
            for (int i = 0; i < 4; i++) sacc[nt][i] = 0.f;

#pragma unroll
        for (int kk = 0; kk < 4; kk++) {
            int c = kk * 16;
            unsigned af[4], bf[4][4];
            ldsm_x4(af, shQ + (unsigned)(a_off + c) * 2);
#pragma unroll
            for (int p = 0; p < 4; p++)
                ldsm_x4(bf[p], shK + (unsigned)(b_off + p * 16 * AST + c) * 2);
#pragma unroll
            for (int nt = 0; nt < 8; nt++)
                mma_f16(sacc[nt], af, &bf[nt >> 1][(nt & 1) * 2]);
        }

        // Mask + online softmax
        float rmax0 = -1e30f, rmax1 = -1e30f;
#pragma unroll
        for (int nt = 0; nt < 8; nt++) {
#pragma unroll
            for (int e = 0; e < 2; e++) {
                int j = cs + nt * 8 + 2 * t + e;
                if (!((j <= iq0) && (j > iq0 - WIN))) sacc[nt][e] = -1e30f;
                if (!((j <= iq1) && (j > iq1 - WIN))) sacc[nt][2 + e] = -1e30f;
                rmax0 = fmaxf(rmax0, sacc[nt][e]);
                rmax1 = fmaxf(rmax1, sacc[nt][2 + e]);
            }
        }
#pragma unroll
        for (int msk = 1; msk < 4; msk <<= 1) {
            rmax0 = fmaxf(rmax0, __shfl_xor_sync(0xffffffffu, rmax0, msk));
            rmax1 = fmaxf(rmax1, __shfl_xor_sync(0xffffffffu, rmax1, msk));
        }

        float mn0 = fmaxf(m0, rmax0);
        float mn1 = fmaxf(m1, rmax1);
        float cor0 = __expf(m0 - mn0);
        float cor1 = __expf(m1 - mn1);
        m0 = mn0; m1 = mn1;

        float rs0 = 0.f, rs1 = 0.f;
#pragma unroll
        for (int nt = 0; nt < 8; nt++) {
            float p0 = __expf(sacc[nt][0] - mn0);
            float p1 = __expf(sacc[nt][1] - mn0);
            float p2 = __expf(sacc[nt][2] - mn1);
            float p3 = __expf(sacc[nt][3] - mn1);
            rs0 += p0 + p1;
            rs1 += p2 + p3;
            int col = nt * 8 + 2 * t;
            *(__half2*)(Ps + (rbase + g) * AST + col)     = __floats2half2_rn(p0, p1);
            *(__half2*)(Ps + (rbase + g + 8) * AST + col) = __floats2half2_rn(p2, p3);
        }
#pragma unroll
        for (int msk = 1; msk < 4; msk <<= 1) {
            rs0 += __shfl_xor_sync(0xffffffffu, rs0, msk);
            rs1 += __shfl_xor_sync(0xffffffffu, rs1, msk);
        }
        l0 = l0 * cor0 + rs0;
        l1 = l1 * cor1 + rs1;
#pragma unroll
        for (int nt = 0; nt < 8; nt++) {
            oacc[nt][0] *= cor0; oacc[nt][1] *= cor0;
            oacc[nt][2] *= cor1; oacc[nt][3] *= cor1;
        }
        __syncwarp();

        // O += P * V
#pragma unroll
        for (int kk = 0; kk < 4; kk++) {
            int c = kk * 16;
            unsigned af[4], bf[4][4];
            ldsm_x4(af, shP + (unsigned)(a_off + c) * 2);
#pragma unroll
            for (int p = 0; p < 4; p++)
                ldsm_x4(bf[p], shV + (unsigned)(b_off + p * 16 * AST + c) * 2);
#pragma unroll
            for (int nt = 0; nt < 8; nt++)
                mma_f16(oacc[nt], af, &bf[nt >> 1][(nt & 1) * 2]);
        }
    }

    // Normalize + write fp16 O (consumed by gemm<1>)
    float inv0 = 1.f / l0;
    float inv1 = 1.f / l1;
    int b = bh / NHEADS;
    int h = bh % NHEADS;
    __half* O0 = g_O + (size_t)(b * SEQ + iq0) * D_MODEL + h * HD;
    __half* O1 = g_O + (size_t)(b * SEQ + iq1) * D_MODEL + h * HD;
#pragma unroll
    for (int nt = 0; nt < 8; nt++) {
        int d = nt * 8 + 2 * t;
        *(__half2*)(O0 + d) = __floats2half2_rn(oacc[nt][0] * inv0, oacc[nt][1] * inv0);
        *(__half2*)(O1 + d) = __floats2half2_rn(oacc[nt][2] * inv1, oacc[nt][3] * inv1);
    }
}

// ---------------------------------------------------------------------------
extern "C" void kernel_launch(void* const* d_in, const int* in_sizes, int n_in,
                              void* d_out, int out_size)
{
    const float* x  = (const float*)d_in[0];
    const float* w1 = (const float*)d_in[1];
    const float* b1 = (const float*)d_in[2];
    const float* w2 = (const float*)d_in[3];
    const float* b2 = (const float*)d_in[4];
    float* out = (float*)d_out;

    const int M = BATCH * SEQ;

    __half *cx, *cw1, *cw2;
    cudaGetSymbolAddress((void**)&cx,  c_x);
    cudaGetSymbolAddress((void**)&cw1, c_w1);
    cudaGetSymbolAddress((void**)&cw2, c_w2);

    // 0) fp32 -> fp16 conversions
    {
        int n4x = M * D_MODEL / 4;
        cvt_f16<<<(n4x + 255) / 256, 256>>>((const float4*)x, (uint2*)cx, n4x);
        int n4w1 = 3 * D_MODEL * D_MODEL / 4;
        cvt_f16<<<(n4w1 + 255) / 256, 256>>>((const float4*)w1, (uint2*)cw1, n4w1);
        int n4w2 = D_MODEL * D_MODEL / 4;
        cvt_f16<<<(n4w2 + 255) / 256, 256>>>((const float4*)w2, (uint2*)cw2, n4w2);
    }

    const int gemm_smem = 2 * NSTG * STG_BYTES;   // 61440 B

    // 1) QKV projection (fp16 mma), routed into g_Q/g_K/g_V
    {
        cudaFuncSetAttribute(gemm_f16<0>,
                             cudaFuncAttributeMaxDynamicSharedMemorySize, gemm_smem);
        dim3 grid(3 * D_MODEL / 128, M / 128);
        gemm_f16<0><<<grid, 256, gemm_smem>>>(cx, cw1, b1, nullptr, M, 3 * D_MODEL, D_MODEL);
    }

    // 2) Sliding-window attention (fp16 mma)
    {
        int smem = 4 * 64 * AST * sizeof(__half);  // 36864 B
        cudaFuncSetAttribute(attn_mma,
                             cudaFuncAttributeMaxDynamicSharedMemorySize, smem);
        dim3 grid(SEQ / 64, BATCH * NHEADS);
        attn_mma<<<grid, 128, smem>>>();
    }

    // 3) Output projection (fp16 mma)
    {
        cudaFuncSetAttribute(gemm_f16<1>,
                             cudaFuncAttributeMaxDynamicSharedMemorySize, gemm_smem);
        dim3 grid(D_MODEL / 128, M / 128);
        gemm_f16<1><<<grid, 256, gemm_smem>>>(nullptr, cw2, b2, out, M, D_MODEL, D_MODEL);
    }
}

// round 9
// speedup vs baseline: 1.9830x; 1.0945x over previous
#include <cuda_runtime.h>
#include <cuda_fp16.h>
#include <math.h>
#include <stdint.h>

#define D_MODEL 1024
#define NHEADS  16
#define HD      64
#define SEQ     2048
#define BATCH   2
#define WIN     256

// Scratch (allocation-free: __device__ globals). All fp16.
__device__ __half g_Q[BATCH * NHEADS * SEQ * HD];   // [b][h][l][d]
__device__ __half g_K[BATCH * NHEADS * SEQ * HD];
__device__ __half g_V[BATCH * NHEADS * SEQ * HD];
__device__ __half g_O[BATCH * SEQ * D_MODEL];       // [b][l][h*64+d]
__device__ __half c_x [BATCH * SEQ * D_MODEL];
__device__ __half c_w1[3 * D_MODEL * D_MODEL];
__device__ __half c_w2[D_MODEL * D_MODEL];

__device__ __forceinline__ void mma_f16(float c[4], const unsigned a[4], const unsigned b[2]) {
    asm volatile(
        "mma.sync.aligned.m16n8k16.row.col.f32.f16.f16.f32 "
        "{%0,%1,%2,%3}, {%4,%5,%6,%7}, {%8,%9}, {%0,%1,%2,%3};\n"
        : "+f"(c[0]), "+f"(c[1]), "+f"(c[2]), "+f"(c[3])
        : "r"(a[0]), "r"(a[1]), "r"(a[2]), "r"(a[3]),
          "r"(b[0]), "r"(b[1]));
}

__device__ __forceinline__ void ldsm_x4(unsigned a[4], unsigned saddr) {
    asm volatile("ldmatrix.sync.aligned.m8n8.x4.shared.b16 {%0,%1,%2,%3}, [%4];"
        : "=r"(a[0]), "=r"(a[1]), "=r"(a[2]), "=r"(a[3]) : "r"(saddr));
}

// ---------------------------------------------------------------------------
// fp32 -> fp16 bulk converter
// ---------------------------------------------------------------------------
__global__ void cvt_f16(const float4* __restrict__ in, uint2* __restrict__ out, int n4)
{
    int i = blockIdx.x * blockDim.x + threadIdx.x;
    if (i < n4) {
        float4 v = in[i];
        __half2 h01 = __floats2half2_rn(v.x, v.y);
        __half2 h23 = __floats2half2_rn(v.z, v.w);
        uint2 u;
        u.x = *(unsigned*)&h01;
        u.y = *(unsigned*)&h23;
        out[i] = u;
    }
}

// ---------------------------------------------------------------------------
// FP16 NT GEMM (fp32 accum), BK=64, 3-stage cp.async pipeline + ldmatrix.
// One barrier per 64-deep k-tile (16 tiles for K=1024).
// C[m,n] = sum_k A[m,k]*W[n,k] + bias[n].  BM=BN=128, 256 thr (2x4 warps).
// Smem rows: 64 halves data, stride SSTR=72 halves (144B) -> LDSM conflict-free.
// ---------------------------------------------------------------------------
#define SSTR 72
#define BK   64
#define STG_HALVES (128 * SSTR)             // per A (or B) stage (9216)
#define STG_BYTES  (STG_HALVES * 2)         // 18432
#define NSTG 3

template <int MODE>
__global__ __launch_bounds__(256, 2)
void gemm_f16(const __half* __restrict__ A, const __half* __restrict__ W,
              const float* __restrict__ bias, float* __restrict__ Cout,
              int M, int N, int K)
{
    extern __shared__ __half sh[];
    __half* AsBase = sh;                        // NSTG stages of A
    __half* BsBase = sh + NSTG * STG_HALVES;    // NSTG stages of B

    const __half* Ap = (MODE == 1) ? (const __half*)g_O : A;

    int tid  = threadIdx.x;
    int lane = tid & 31;
    int wid  = tid >> 5;
    int wm = (wid >> 2) * 64;
    int wn = (wid & 3) * 32;
    int bm = blockIdx.y * 128;
    int bn = blockIdx.x * 128;
    int g = lane >> 2;
    int t = lane & 3;
    int lr = lane & 7;

    // ldmatrix source offsets (in halves)
    int a_off = (wm + lr + (((lane >> 3) & 1) ? 8 : 0)) * SSTR + ((lane >> 4) ? 8 : 0);
    int b_off = (wn + lr + ((lane >> 4) ? 8 : 0)) * SSTR + (((lane >> 3) & 1) ? 8 : 0);

    unsigned shA = (unsigned)__cvta_generic_to_shared(AsBase);
    unsigned shB = (unsigned)__cvta_generic_to_shared(BsBase);

    float acc[4][4][4];
#pragma unroll
    for (int mt = 0; mt < 4; mt++)
#pragma unroll
        for (int nt = 0; nt < 4; nt++)
#pragma unroll
            for (int i = 0; i < 4; i++) acc[mt][nt][i] = 0.f;

    // Per tile: A = 128 rows x 128B = 1024 x 16B chunks; same for B.
    // 256 threads -> 4 A-chunks + 4 B-chunks per thread.
    auto issue = [&](int s, int k0) {
        __half* dA = AsBase + s * STG_HALVES;
        __half* dB = BsBase + s * STG_HALVES;
#pragma unroll
        for (int r = 0; r < 4; r++) {
            int id  = tid + r * 256;        // 0..1023
            int row = id >> 3;
            int c   = id & 7;               // 16B chunk within 128B row
            const __half* ga = Ap + (size_t)(bm + row) * K + k0 + c * 8;
            const __half* gb = W  + (size_t)(bn + row) * K + k0 + c * 8;
            unsigned sa = (unsigned)__cvta_generic_to_shared(dA + row * SSTR + c * 8);
            unsigned sb = (unsigned)__cvta_generic_to_shared(dB + row * SSTR + c * 8);
            asm volatile("cp.async.cg.shared.global [%0], [%1], 16;\n" :: "r"(sa), "l"(ga));
            asm volatile("cp.async.cg.shared.global [%0], [%1], 16;\n" :: "r"(sb), "l"(gb));
        }
        asm volatile("cp.async.commit_group;\n");
    };

    const int TILES = K / BK;   // 16
    issue(0, 0);
    issue(1, BK);

    int stage = 0, fill = 2;

    for (int t2 = 0; t2 < TILES; t2++) {
        asm volatile("cp.async.wait_group 1;\n" ::: "memory");
        __syncthreads();

        if (t2 + 2 < TILES) issue(fill, (t2 + 2) * BK);

        unsigned stA = shA + stage * STG_BYTES;
        unsigned stB = shB + stage * STG_BYTES;

#pragma unroll
        for (int ks = 0; ks < 4; ks++) {
            int kk = ks * 16;
            unsigned af[4][4], bf[2][4];
#pragma unroll
            for (int mt = 0; mt < 4; mt++)
                ldsm_x4(af[mt], stA + (unsigned)(a_off + mt * 16 * SSTR + kk) * 2);
#pragma unroll
            for (int p = 0; p < 2; p++)
                ldsm_x4(bf[p], stB + (unsigned)(b_off + p * 16 * SSTR + kk) * 2);
#pragma unroll
            for (int mt = 0; mt < 4; mt++)
#pragma unroll
                for (int nt = 0; nt < 4; nt++)
                    mma_f16(acc[mt][nt], af[mt], &bf[nt >> 1][(nt & 1) * 2]);
        }

        fill  = stage;
        stage = (stage == 2) ? 0 : stage + 1;
    }

#pragma unroll
    for (int mt = 0; mt < 4; mt++) {
#pragma unroll
        for (int nt = 0; nt < 4; nt++) {
#pragma unroll
            for (int i = 0; i < 4; i++) {
                int m = bm + wm + mt * 16 + g + ((i >> 1) ? 8 : 0);
                int n = bn + wn + nt * 8 + t * 2 + (i & 1);
                float v = acc[mt][nt][i] + bias[n];
                if (MODE == 0) {
                    int part   = n >> 10;
                    int within = n & 1023;
                    int h = within >> 6;
                    int d = within & 63;
                    int b = m >> 11;
                    int l = m & 2047;
                    size_t dst = ((size_t)(b * NHEADS + h) * SEQ + l) * HD + d;
                    __half* base = (part == 0) ? g_Q : (part == 1) ? g_K : g_V;
                    base[dst] = __float2half_rn(v);
                } else {
                    Cout[(size_t)m * N + n] = v;
                }
            }
        }
    }
}

// ---------------------------------------------------------------------------
// Sliding-window attention, fp16 mma (fp32 accum/softmax) + ldmatrix.
// One CTA = (b*h, 64-query tile), 128 threads (4 warps, warp = 16 query rows).
// (unchanged from R8)
// ---------------------------------------------------------------------------
#define AST 72

__global__ __launch_bounds__(128)
void attn_mma()
{
    extern __shared__ __half smh[];
    __half* Qs = smh;                 // [q][d]  64 x AST
    __half* Ks = smh + 64 * AST;      // [j][d]
    __half* Vt = smh + 2 * 64 * AST;  // [d][j]
    __half* Ps = smh + 3 * 64 * AST;  // [q][j]

    int tid  = threadIdx.x;
    int lane = tid & 31;
    int wid  = tid >> 5;
    int g = lane >> 2;
    int t = lane & 3;
    int lr = lane & 7;

    int bh = blockIdx.y;
    int i0 = blockIdx.x * 64;

    const __half* Qg = g_Q + (size_t)bh * SEQ * HD;
    const __half* Kg = g_K + (size_t)bh * SEQ * HD;
    const __half* Vg = g_V + (size_t)bh * SEQ * HD;

    int rbase = wid * 16;
    int a_off = (rbase + lr + (((lane >> 3) & 1) ? 8 : 0)) * AST + ((lane >> 4) ? 8 : 0);
    int b_off = (lr + ((lane >> 4) ? 8 : 0)) * AST + (((lane >> 3) & 1) ? 8 : 0);

    unsigned shQ = (unsigned)__cvta_generic_to_shared(Qs);
    unsigned shK = (unsigned)__cvta_generic_to_shared(Ks);
    unsigned shV = (unsigned)__cvta_generic_to_shared(Vt);
    unsigned shP = (unsigned)__cvta_generic_to_shared(Ps);

    {
        int q = tid >> 1, half_sel = tid & 1;
        const __half2 s2 = __floats2half2_rn(0.125f, 0.125f);
#pragma unroll
        for (int v = 0; v < 4; v++) {
            int c8 = half_sel * 32 + v * 8;
            uint2 raw = *(const uint2*)(Qg + (size_t)(i0 + q) * HD + c8);
            __half2 h0 = __hmul2(*(__half2*)&raw.x, s2);
            __half2 h1 = __hmul2(*(__half2*)&raw.y, s2);
            uint2 raw2 = *(const uint2*)(Qg + (size_t)(i0 + q) * HD + c8 + 4);
            __half2 h2 = __hmul2(*(__half2*)&raw2.x, s2);
            __half2 h3 = __hmul2(*(__half2*)&raw2.y, s2);
            __half* dst = Qs + q * AST + c8;
            *(__half2*)(dst)     = h0;
            *(__half2*)(dst + 2) = h1;
            *(__half2*)(dst + 4) = h2;
            *(__half2*)(dst + 6) = h3;
        }
    }

    int iq0 = i0 + rbase + g;
    int iq1 = iq0 + 8;

    float m0 = -1e30f, m1 = -1e30f, l0 = 0.f, l1 = 0.f;
    float oacc[8][4];
#pragma unroll
    for (int nt = 0; nt < 8; nt++)
#pragma unroll
        for (int i = 0; i < 4; i++) oacc[nt][i] = 0.f;

    int kv_lo = i0 - (WIN - 1);
    if (kv_lo < 0) kv_lo = 0;
    int cs0 = (kv_lo / 64) * 64;

    for (int cs = cs0; cs <= i0; cs += 64) {
        __syncthreads();
        {
            int j = tid >> 1, half_sel = tid & 1;
#pragma unroll
            for (int v = 0; v < 2; v++) {
                int c16 = half_sel * 32 + v * 16;
                uint4 kraw = *(const uint4*)(Kg + (size_t)(cs + j) * HD + c16);
                *(uint4*)(Ks + j * AST + c16) = kraw;
                uint4 kraw2 = *(const uint4*)(Kg + (size_t)(cs + j) * HD + c16 + 8);
                *(uint4*)(Ks + j * AST + c16 + 8) = kraw2;

                uint4 vraw = *(const uint4*)(Vg + (size_t)(cs + j) * HD + c16);
                const __half* vh = (const __half*)&vraw;
#pragma unroll
                for (int e = 0; e < 8; e++)
                    Vt[(c16 + e) * AST + j] = vh[e];
                uint4 vraw2 = *(const uint4*)(Vg + (size_t)(cs + j) * HD + c16 + 8);
                const __half* vh2 = (const __half*)&vraw2;
#pragma unroll
                for (int e = 0; e < 8; e++)
                    Vt[(c16 + 8 + e) * AST + j] = vh2[e];
            }
        }
        __syncthreads();

        float sacc[8][4];
#pragma unroll
        for (int nt = 0; nt < 8; nt++)
#pragma unroll
            for (int i = 0; i < 4; i++) sacc[nt][i] = 0.f;

#pragma unroll
        for (int kk = 0; kk < 4; kk++) {
            int c = kk * 16;
            unsigned af[4], bf[4][4];
            ldsm_x4(af, shQ + (unsigned)(a_off + c) * 2);
#pragma unroll
            for (int p = 0; p < 4; p++)
                ldsm_x4(bf[p], shK + (unsigned)(b_off + p * 16 * AST + c) * 2);
#pragma unroll
            for (int nt = 0; nt < 8; nt++)
                mma_f16(sacc[nt], af, &bf[nt >> 1][(nt & 1) * 2]);
        }

        float rmax0 = -1e30f, rmax1 = -1e30f;
#pragma unroll
        for (int nt = 0; nt < 8; nt++) {
#pragma unroll
            for (int e = 0; e < 2; e++) {
                int j = cs + nt * 8 + 2 * t + e;
                if (!((j <= iq0) && (j > iq0 - WIN))) sacc[nt][e] = -1e30f;
                if (!((j <= iq1) && (j > iq1 - WIN))) sacc[nt][2 + e] = -1e30f;
                rmax0 = fmaxf(rmax0, sacc[nt][e]);
                rmax1 = fmaxf(rmax1, sacc[nt][2 + e]);
            }
        }
#pragma unroll
        for (int msk = 1; msk < 4; msk <<= 1) {
            rmax0 = fmaxf(rmax0, __shfl_xor_sync(0xffffffffu, rmax0, msk));
            rmax1 = fmaxf(rmax1, __shfl_xor_sync(0xffffffffu, rmax1, msk));
        }

        float mn0 = fmaxf(m0, rmax0);
        float mn1 = fmaxf(m1, rmax1);
        float cor0 = __expf(m0 - mn0);
        float cor1 = __expf(m1 - mn1);
        m0 = mn0; m1 = mn1;

        float rs0 = 0.f, rs1 = 0.f;
#pragma unroll
        for (int nt = 0; nt < 8; nt++) {
            float p0 = __expf(sacc[nt][0] - mn0);
            float p1 = __expf(sacc[nt][1] - mn0);
            float p2 = __expf(sacc[nt][2] - mn1);
            float p3 = __expf(sacc[nt][3] - mn1);
            rs0 += p0 + p1;
            rs1 += p2 + p3;
            int col = nt * 8 + 2 * t;
            *(__half2*)(Ps + (rbase + g) * AST + col)     = __floats2half2_rn(p0, p1);
            *(__half2*)(Ps + (rbase + g + 8) * AST + col) = __floats2half2_rn(p2, p3);
        }
#pragma unroll
        for (int msk = 1; msk < 4; msk <<= 1) {
            rs0 += __shfl_xor_sync(0xffffffffu, rs0, msk);
            rs1 += __shfl_xor_sync(0xffffffffu, rs1, msk);
        }
        l0 = l0 * cor0 + rs0;
        l1 = l1 * cor1 + rs1;
#pragma unroll
        for (int nt = 0; nt < 8; nt++) {
            oacc[nt][0] *= cor0; oacc[nt][1] *= cor0;
            oacc[nt][2] *= cor1; oacc[nt][3] *= cor1;
        }
        __syncwarp();

#pragma unroll
        for (int kk = 0; kk < 4; kk++) {
            int c = kk * 16;
            unsigned af[4], bf[4][4];
            ldsm_x4(af, shP + (unsigned)(a_off + c) * 2);
#pragma unroll
            for (int p = 0; p < 4; p++)
                ldsm_x4(bf[p], shV + (unsigned)(b_off + p * 16 * AST + c) * 2);
#pragma unroll
            for (int nt = 0; nt < 8; nt++)
                mma_f16(oacc[nt], af, &bf[nt >> 1][(nt & 1) * 2]);
        }
    }

    float inv0 = 1.f / l0;
    float inv1 = 1.f / l1;
    int b = bh / NHEADS;
    int h = bh % NHEADS;
    __half* O0 = g_O + (size_t)(b * SEQ + iq0) * D_MODEL + h * HD;
    __half* O1 = g_O + (size_t)(b * SEQ + iq1) * D_MODEL + h * HD;
#pragma unroll
    for (int nt = 0; nt < 8; nt++) {
        int d = nt * 8 + 2 * t;
        *(__half2*)(O0 + d) = __floats2half2_rn(oacc[nt][0] * inv0, oacc[nt][1] * inv0);
        *(__half2*)(O1 + d) = __floats2half2_rn(oacc[nt][2] * inv1, oacc[nt][3] * inv1);
    }
}

// ---------------------------------------------------------------------------
extern "C" void kernel_launch(void* const* d_in, const int* in_sizes, int n_in,
                              void* d_out, int out_size)
{
    const float* x  = (const float*)d_in[0];
    const float* w1 = (const float*)d_in[1];
    const float* b1 = (const float*)d_in[2];
    const float* w2 = (const float*)d_in[3];
    const float* b2 = (const float*)d_in[4];
    float* out = (float*)d_out;

    const int M = BATCH * SEQ;

    __half *cx, *cw1, *cw2;
    cudaGetSymbolAddress((void**)&cx,  c_x);
    cudaGetSymbolAddress((void**)&cw1, c_w1);
    cudaGetSymbolAddress((void**)&cw2, c_w2);

    // 0) fp32 -> fp16 conversions
    {
        int n4x = M * D_MODEL / 4;
        cvt_f16<<<(n4x + 255) / 256, 256>>>((const float4*)x, (uint2*)cx, n4x);
        int n4w1 = 3 * D_MODEL * D_MODEL / 4;
        cvt_f16<<<(n4w1 + 255) / 256, 256>>>((const float4*)w1, (uint2*)cw1, n4w1);
        int n4w2 = D_MODEL * D_MODEL / 4;
        cvt_f16<<<(n4w2 + 255) / 256, 256>>>((const float4*)w2, (uint2*)cw2, n4w2);
    }

    const int gemm_smem = 2 * NSTG * STG_BYTES;   // 110592 B

    // 1) QKV projection (fp16 mma, BK=64 pipeline)
    {
        cudaFuncSetAttribute(gemm_f16<0>,
                             cudaFuncAttributeMaxDynamicSharedMemorySize, gemm_smem);
        dim3 grid(3 * D_MODEL / 128, M / 128);
        gemm_f16<0><<<grid, 256, gemm_smem>>>(cx, cw1, b1, nullptr, M, 3 * D_MODEL, D_MODEL);
    }

    // 2) Sliding-window attention (fp16 mma)
    {
        int smem = 4 * 64 * AST * sizeof(__half);  // 36864 B
        cudaFuncSetAttribute(attn_mma,
                             cudaFuncAttributeMaxDynamicSharedMemorySize, smem);
        dim3 grid(SEQ / 64, BATCH * NHEADS);
        attn_mma<<<grid, 128, smem>>>();
    }

    // 3) Output projection (fp16 mma)
    {
        cudaFuncSetAttribute(gemm_f16<1>,
                             cudaFuncAttributeMaxDynamicSharedMemorySize, gemm_smem);
        dim3 grid(D_MODEL / 128, M / 128);
        gemm_f16<1><<<grid, 256, gemm_smem>>>(nullptr, cw2, b2, out, M, D_MODEL, D_MODEL);
    }
}